// round 6
// baseline (speedup 1.0000x reference)
#include <cuda_runtime.h>
#include <math.h>
#include <stdint.h>

#define SLICE 32768      // 512*64 floats per (b,f) slice
#define HALF  16384      // per-rank half of a slice
#define M_HALF 256
#define NTHREADS 512
#define NSLICES 64       // B*C = 4*16

typedef unsigned long long ull;

__device__ float g_bufs[(size_t)NSLICES * 5 * SLICE];
__device__ float g_acc[(size_t)NSLICES * SLICE];

// Dynamic shared layout
struct SmemT {
    float As2[2][16][512];   // duplicated A tiles: As2[k][2n]=As2[k][2n+1]=A[n][k]  (64 KB)
    float Bs[2][16][64];     // spatial B staging                                    (8 KB)
    float Lt[64][64];        // persistent temporal operator                         (16 KB)
};

#define CLUSTER_SYNC() do { \
    asm volatile("barrier.cluster.arrive.aligned;" ::: "memory"); \
    asm volatile("barrier.cluster.wait.aligned;" ::: "memory"); \
} while (0)

__device__ __forceinline__ uint32_t smem_u32(const void* p) {
    uint32_t a;
    asm("{ .reg .u64 t; cvta.to.shared.u64 t, %1; cvt.u32.u64 %0, t; }" : "=r"(a) : "l"(p));
    return a;
}

__device__ __forceinline__ float dsmem_peer_f32(uint32_t smem_addr, uint32_t peer) {
    uint32_t ra;
    asm volatile("mapa.shared::cluster.u32 %0, %1, %2;" : "=r"(ra) : "r"(smem_addr), "r"(peer));
    float v;
    asm volatile("ld.shared::cluster.f32 %0, [%1];" : "=f"(v) : "r"(ra));
    return v;
}

// ---------------- packed f32x2 helpers ----------------
__device__ __forceinline__ void fma2_acc(ull& d, ull a, ull b) {
    asm("fma.rn.f32x2 %0, %1, %2, %0;" : "+l"(d) : "l"(a), "l"(b));
}
__device__ __forceinline__ ull fma2(ull a, ull b, ull c) {
    ull d;
    asm("fma.rn.f32x2 %0, %1, %2, %3;" : "=l"(d) : "l"(a), "l"(b), "l"(c));
    return d;
}
__device__ __forceinline__ ull mul2(ull a, ull b) {
    ull d;
    asm("mul.rn.f32x2 %0, %1, %2;" : "=l"(d) : "l"(a), "l"(b));
    return d;
}
__device__ __forceinline__ ull splat2(float x) {
    ull d;
    uint32_t u = __float_as_uint(x);
    asm("mov.b64 %0, {%1, %1};" : "=l"(d) : "r"(u));
    return d;
}
__device__ __forceinline__ float2 unpack2(ull v) {
    uint32_t lo, hi;
    asm("mov.b64 {%0, %1}, %2;" : "=r"(lo), "=r"(hi) : "l"(v));
    return make_float2(__uint_as_float(lo), __uint_as_float(hi));
}
__device__ __forceinline__ float hsum2(ull v) { float2 f = unpack2(v); return f.x + f.y; }

// ---------------- fused 3-value block reduction ----------------
__device__ __forceinline__ void block_sum3(float& a, float& b, float& c, float (*red)[32]) {
    #pragma unroll
    for (int o = 16; o; o >>= 1) {
        a += __shfl_xor_sync(0xffffffffu, a, o);
        b += __shfl_xor_sync(0xffffffffu, b, o);
        c += __shfl_xor_sync(0xffffffffu, c, o);
    }
    int w = threadIdx.x >> 5, l = threadIdx.x & 31;
    if (l == 0) { red[0][w] = a; red[1][w] = b; red[2][w] = c; }
    __syncthreads();
    if (w == 0) {
        float ta = (l < 16) ? red[0][l] : 0.f;
        float tb = (l < 16) ? red[1][l] : 0.f;
        float tc = (l < 16) ? red[2][l] : 0.f;
        #pragma unroll
        for (int o = 8; o; o >>= 1) {
            ta += __shfl_xor_sync(0xffffffffu, ta, o);
            tb += __shfl_xor_sync(0xffffffffu, tb, o);
            tc += __shfl_xor_sync(0xffffffffu, tc, o);
        }
        if (l == 0) { red[0][0] = ta; red[1][0] = tb; red[2][0] = tc; }
    }
    __syncthreads();
    a = red[0][0]; b = red[1][0]; c = red[2][0];
    __syncthreads();
}

// stage one A tile with value duplication (enables free f32x2 splats on load)
__device__ __forceinline__ void stage_dup(float (*dst)[512], int kh, int rl,
                                          float4 a0, float4 a1) {
    *(float2*)&dst[kh + 0][2 * rl] = make_float2(a0.x, a0.x);
    *(float2*)&dst[kh + 1][2 * rl] = make_float2(a0.y, a0.y);
    *(float2*)&dst[kh + 2][2 * rl] = make_float2(a0.z, a0.z);
    *(float2*)&dst[kh + 3][2 * rl] = make_float2(a0.w, a0.w);
    *(float2*)&dst[kh + 4][2 * rl] = make_float2(a1.x, a1.x);
    *(float2*)&dst[kh + 5][2 * rl] = make_float2(a1.y, a1.y);
    *(float2*)&dst[kh + 6][2 * rl] = make_float2(a1.z, a1.z);
    *(float2*)&dst[kh + 7][2 * rl] = make_float2(a1.w, a1.w);
}

// ---------------- one basis step (per-rank half of the M dimension) ----------------
// rst = A @ B (my 256 rows); analytic-norm Gram-Schmidt epilogue; acc += th*dst.
// Packed f32x2 along the t dimension throughout.
template<bool SPATIAL>
__device__ void basis_step(const float* __restrict__ A,
                           const float* __restrict__ Bg,     // spatial B (global); temporal uses sm->Lt
                           float* __restrict__ dsth,
                           const float* __restrict__ lasth,
                           const float* __restrict__ sech,
                           float th, float* __restrict__ acch,
                           SmemT* sm, float (*red)[32],
                           float* xch, uint32_t xch_addr, uint32_t peer,
                           int phase, bool trail)
{
    constexpr int K = SPATIAL ? 512 : 64;
    constexpr int LDA = SPATIAL ? 512 : 64;
    constexpr int TILES = K / 16;

    const int tid = threadIdx.x;
    const int rl  = tid >> 1;          // staging row 0..255
    const int kh  = (tid & 1) * 8;     // which 8 of 16 k's this thread stages
    const int n0  = (tid >> 3) * 4;    // 4-row group
    const int t0  = (tid & 7) * 8;     // 8-col group (4 packed t-pairs)
    const bool has_sec = (sech != nullptr);

    ull av2[4][4];
    #pragma unroll
    for (int i = 0; i < 4; i++)
        #pragma unroll
        for (int j = 0; j < 4; j++) av2[i][j] = 0ull;

    // ---- prologue: stage tile 0 ----
    {
        const float* ar = A + (size_t)rl * LDA + kh;
        float4 a0 = *(const float4*)(ar);
        float4 a1 = *(const float4*)(ar + 4);
        stage_dup(sm->As2[0], kh, rl, a0, a1);
        if (SPATIAL && tid < 256)
            ((float4*)&sm->Bs[0][0][0])[tid] = __ldcg((const float4*)Bg + tid);
    }
    __syncthreads();

    int p = 0;
    for (int t = 0; t < TILES; t++) {
        float4 na0, na1, nbv;
        const bool more = (t + 1 < TILES);
        if (more) {
            const int kt = (t + 1) * 16;
            const float* ar = A + (size_t)rl * LDA + kt + kh;
            na0 = *(const float4*)(ar);
            na1 = *(const float4*)(ar + 4);
            if (SPATIAL && tid < 256)
                nbv = __ldcg((const float4*)(Bg + (size_t)kt * 64) + tid);
        }

        const int ktb = t * 16;
        #pragma unroll
        for (int k = 0; k < 16; k++) {
            ulonglong2 a01 = *(const ulonglong2*)&sm->As2[p][k][2 * n0];      // {a0,a0},{a1,a1}
            ulonglong2 a23 = *(const ulonglong2*)&sm->As2[p][k][2 * n0 + 4];  // {a2,a2},{a3,a3}
            const float* brow = SPATIAL ? &sm->Bs[p][k][t0] : &sm->Lt[ktb + k][t0];
            ulonglong2 b01 = *(const ulonglong2*)brow;
            ulonglong2 b23 = *(const ulonglong2*)(brow + 4);
            ull a[4] = {a01.x, a01.y, a23.x, a23.y};
            ull b[4] = {b01.x, b01.y, b23.x, b23.y};
            #pragma unroll
            for (int i = 0; i < 4; i++)
                #pragma unroll
                for (int j = 0; j < 4; j++)
                    fma2_acc(av2[i][j], a[i], b[j]);
        }

        if (more) {
            const int q = p ^ 1;
            stage_dup(sm->As2[q], kh, rl, na0, na1);
            if (SPATIAL && tid < 256) ((float4*)&sm->Bs[q][0][0])[tid] = nbv;
            __syncthreads();
            p = q;
        }
    }

    // ---- epilogue: packed dots + norm from registers ----
    ull pd1_2 = 0ull, pd2_2 = 0ull, pr2_2 = 0ull;
    ull lv2[4][4];
    #pragma unroll
    for (int i = 0; i < 4; i++) {
        size_t base = (size_t)(n0 + i) * 64 + t0;
        ulonglong2 lA = *(const ulonglong2*)(lasth + base);
        ulonglong2 lB = *(const ulonglong2*)(lasth + base + 4);
        lv2[i][0] = lA.x; lv2[i][1] = lA.y; lv2[i][2] = lB.x; lv2[i][3] = lB.y;
        #pragma unroll
        for (int j = 0; j < 4; j++) {
            fma2_acc(pd1_2, av2[i][j], lv2[i][j]);
            fma2_acc(pr2_2, av2[i][j], av2[i][j]);
        }
        if (has_sec) {
            ulonglong2 sA = *(const ulonglong2*)(sech + base);
            ulonglong2 sB = *(const ulonglong2*)(sech + base + 4);
            fma2_acc(pd2_2, av2[i][0], sA.x);
            fma2_acc(pd2_2, av2[i][1], sA.y);
            fma2_acc(pd2_2, av2[i][2], sB.x);
            fma2_acc(pd2_2, av2[i][3], sB.y);
        }
    }
    float pd1 = hsum2(pd1_2), pd2 = hsum2(pd2_2), pr2 = hsum2(pr2_2);
    block_sum3(pd1, pd2, pr2, red);

    const int xb = phase * 4;
    if (tid == 0) { xch[xb + 0] = pd1; xch[xb + 1] = pd2; xch[xb + 2] = pr2; }
    CLUSTER_SYNC();
    float d1 = pd1 + dsmem_peer_f32(xch_addr + 4 * xb + 0, peer);
    float d2 = has_sec ? (pd2 + dsmem_peer_f32(xch_addr + 4 * xb + 4, peer)) : 0.f;
    float r2 = pr2 + dsmem_peer_f32(xch_addr + 4 * xb + 8, peer);
    float n2 = r2 - d1 * d1 - d2 * d2;
    float inv = 1.f / fmaxf(sqrtf(fmaxf(n2, 0.f)), 1e-8f);

    // ---- write normalized dst + acc update (packed) ----
    ull nd1_2 = splat2(-d1);
    ull nd2_2 = splat2(-d2);
    ull inv2  = splat2(inv);
    ull th2   = splat2(th);
    #pragma unroll
    for (int i = 0; i < 4; i++) {
        size_t base = (size_t)(n0 + i) * 64 + t0;
        ull v[4];
        #pragma unroll
        for (int j = 0; j < 4; j++) v[j] = fma2(nd1_2, lv2[i][j], av2[i][j]);
        if (has_sec) {
            ulonglong2 sA = *(const ulonglong2*)(sech + base);
            ulonglong2 sB = *(const ulonglong2*)(sech + base + 4);
            v[0] = fma2(nd2_2, sA.x, v[0]);
            v[1] = fma2(nd2_2, sA.y, v[1]);
            v[2] = fma2(nd2_2, sB.x, v[2]);
            v[3] = fma2(nd2_2, sB.y, v[3]);
        }
        #pragma unroll
        for (int j = 0; j < 4; j++) v[j] = mul2(v[j], inv2);

        ulonglong2 o0; o0.x = v[0]; o0.y = v[1];
        ulonglong2 o1; o1.x = v[2]; o1.y = v[3];
        *(ulonglong2*)(dsth + base)     = o0;
        *(ulonglong2*)(dsth + base + 4) = o1;

        ulonglong2 aA = *(ulonglong2*)(acch + base);
        ulonglong2 aB = *(ulonglong2*)(acch + base + 4);
        aA.x = fma2(th2, v[0], aA.x);
        aA.y = fma2(th2, v[1], aA.y);
        aB.x = fma2(th2, v[2], aB.x);
        aB.y = fma2(th2, v[3], aB.y);
        *(ulonglong2*)(acch + base)     = aA;
        *(ulonglong2*)(acch + base + 4) = aB;
    }
    if (trail) CLUSTER_SYNC();   // dst visibility to peer — only before spatial steps
}

// ---------------- main kernel: 2-CTA cluster per (b,f) slice ----------------
__global__ void __cluster_dims__(2, 1, 1) __launch_bounds__(NTHREADS, 1)
st_main_kernel(const float* __restrict__ x,
               const float* __restrict__ Ls,
               const float* __restrict__ Lt,
               const float* __restrict__ STE,
               const float* __restrict__ w_t1, const float* __restrict__ b_t1,
               const float* __restrict__ w_t2, const float* __restrict__ b_t2)
{
    extern __shared__ __align__(16) char smem_raw[];
    SmemT* sm = reinterpret_cast<SmemT*>(smem_raw);

    __shared__ float red[3][32];
    __shared__ float theta_sm[66];
    __shared__ float h1_sm[60];
    __shared__ __align__(16) float xch[8];

    const int tid = threadIdx.x;
    const int slice = blockIdx.x >> 1;
    const uint32_t rank = blockIdx.x & 1;
    const uint32_t peer = rank ^ 1;
    const int b = slice >> 4;
    const uint32_t xch_addr = smem_u32(xch);
    const size_t hoff = (size_t)rank * HALF;

    const float* xs = x + (size_t)slice * SLICE;
    float* acc = g_acc + (size_t)slice * SLICE;
    float* bufp[5];
    #pragma unroll
    for (int i = 0; i < 5; i++) bufp[i] = g_bufs + ((size_t)slice * 5 + i) * SLICE;

    // ---- load Lt into persistent smem ----
    for (int i = tid; i < 64 * 64 / 4; i += NTHREADS)
        ((float4*)&sm->Lt[0][0])[i] = ((const float4*)Lt)[i];

    // ---- theta (tiny MLP on STE), redundantly per CTA ----
    if (tid < 60) {
        int o = tid / 10, s = tid % 10;
        float h = b_t1[o];
        #pragma unroll
        for (int t = 0; t < 5; t++) h = fmaf(w_t1[o * 5 + t], STE[b * 50 + t * 10 + s], h);
        h1_sm[o * 10 + s] = h;
    }
    __syncthreads();
    if (tid < 66) {
        int p = tid % 11, o = tid / 11;
        float h = b_t2[p];
        #pragma unroll
        for (int s = 0; s < 10; s++) h = fmaf(w_t2[p * 10 + s], h1_sm[o * 10 + s], h);
        theta_sm[o * 11 + p] = fmaxf(h, 0.f);   // flat r = o*11 + p matches M order
    }
    __syncthreads();

    // ---- m00 = x / fro(x);  acc = theta[0] * m00  (my half) ----
    float pnv = 0.f, z1 = 0.f, z2 = 0.f;
    const float4* x4 = (const float4*)(xs + hoff);
    for (int i = tid; i < HALF / 4; i += NTHREADS) {
        float4 v = x4[i];
        pnv += v.x * v.x + v.y * v.y + v.z * v.z + v.w * v.w;
    }
    block_sum3(pnv, z1, z2, red);
    if (tid == 0) xch[3] = pnv;
    CLUSTER_SYNC();
    float nv = pnv + dsmem_peer_f32(xch_addr + 12, peer);
    float inv = 1.f / fmaxf(sqrtf(nv), 1e-8f);
    float th0 = theta_sm[0];
    float4* b04 = (float4*)(bufp[0] + hoff);
    float4* a4 = (float4*)(acc + hoff);
    for (int i = tid; i < HALF / 4; i += NTHREADS) {
        float4 v = x4[i];
        v.x *= inv; v.y *= inv; v.z *= inv; v.w *= inv;
        b04[i] = v;
        a4[i] = make_float4(th0 * v.x, th0 * v.y, th0 * v.z, th0 * v.w);
    }
    __syncthreads();   // bufp[0] half complete before step 1 (temporal, own-half only)

    // ---- recurrence ----
    int last_s = 0, sec_s = -1, last_t = 0, sec_t = -1;
    int r = 1;
    for (int i = 0; i <= 10; i++) {
        if (i > 0) {
            int nb = 0;
            while (nb == last_s || nb == sec_s || nb == last_t || nb == sec_t) nb++;
            bool trail = (r % 6 == 5) && (r <= 59);
            basis_step<true>(Ls + (size_t)rank * M_HALF * 512,
                             bufp[last_s],
                             bufp[nb] + hoff,
                             bufp[last_s] + hoff,
                             (sec_s >= 0) ? bufp[sec_s] + hoff : nullptr,
                             theta_sm[r], acc + hoff, sm, red,
                             xch, xch_addr, peer, r & 1, trail);
            sec_s = last_s; last_s = nb;
            last_t = nb; sec_t = -1;
            r++;
        }
        for (int j = 0; j < 5; j++) {
            int nb = 0;
            while (nb == last_s || nb == sec_s || nb == last_t || nb == sec_t) nb++;
            bool trail = (r % 6 == 5) && (r <= 59);
            basis_step<false>(bufp[last_t] + hoff,
                              nullptr,
                              bufp[nb] + hoff,
                              bufp[last_t] + hoff,
                              (sec_t >= 0) ? bufp[sec_t] + hoff : nullptr,
                              theta_sm[r], acc + hoff, sm, red,
                              xch, xch_addr, peer, r & 1, trail);
            sec_t = last_t; last_t = nb;
            r++;
        }
    }
}

// ---------------- output MLP + folded BatchNorm ----------------
__global__ __launch_bounds__(256)
void st_out_kernel(const float* __restrict__ x,
                   const float* __restrict__ w_mlp, const float* __restrict__ b_mlp,
                   const float* __restrict__ gamma, const float* __restrict__ beta,
                   const float* __restrict__ mean, const float* __restrict__ var,
                   float* __restrict__ out)
{
    __shared__ float ws[64][32];
    __shared__ float bs[64];
    const int tid = threadIdx.x;
    for (int i = tid; i < 64 * 32; i += 256) {
        int o = i >> 5;
        float invs = gamma[o] * rsqrtf(var[o] + 1e-5f);
        ws[o][i & 31] = w_mlp[i] * invs;
    }
    if (tid < 64) {
        float invs = gamma[tid] * rsqrtf(var[tid] + 1e-5f);
        bs[tid] = b_mlp[tid] * invs + beta[tid] - mean[tid] * invs;
    }
    __syncthreads();

    const int b = blockIdx.y;
    const int pt = blockIdx.x * 256 + tid;   // 0..32767

    float xv[16], av[16];
    #pragma unroll
    for (int c = 0; c < 16; c++) {
        xv[c] = x[((size_t)(b * 16 + c)) * SLICE + pt];
        av[c] = g_acc[((size_t)(b * 16 + c)) * SLICE + pt];
    }
    #pragma unroll
    for (int o = 0; o < 64; o++) {
        float s = bs[o];
        #pragma unroll
        for (int c = 0; c < 16; c++) {
            s = fmaf(ws[o][c], xv[c], s);
            s = fmaf(ws[o][16 + c], av[c], s);
        }
        out[((size_t)(b * 64 + o)) * SLICE + pt] = s;
    }
}

extern "C" void kernel_launch(void* const* d_in, const int* in_sizes, int n_in,
                              void* d_out, int out_size) {
    const float* x    = (const float*)d_in[0];
    const float* Ls   = (const float*)d_in[1];
    const float* Lt   = (const float*)d_in[2];
    const float* STE  = (const float*)d_in[3];
    const float* w_t1 = (const float*)d_in[4];
    const float* b_t1 = (const float*)d_in[5];
    const float* w_t2 = (const float*)d_in[6];
    const float* b_t2 = (const float*)d_in[7];
    const float* w_mlp = (const float*)d_in[8];
    const float* b_mlp = (const float*)d_in[9];
    const float* gamma = (const float*)d_in[10];
    const float* beta  = (const float*)d_in[11];
    const float* mean  = (const float*)d_in[12];
    const float* var   = (const float*)d_in[13];
    float* out = (float*)d_out;

    cudaFuncSetAttribute(st_main_kernel,
                         cudaFuncAttributeMaxDynamicSharedMemorySize, (int)sizeof(SmemT));
    st_main_kernel<<<NSLICES * 2, NTHREADS, sizeof(SmemT)>>>(
        x, Ls, Lt, STE, w_t1, b_t1, w_t2, b_t2);
    st_out_kernel<<<dim3(128, 4), 256>>>(x, w_mlp, b_mlp, gamma, beta, mean, var, out);
}

// round 8
// speedup vs baseline: 1.1957x; 1.1957x over previous
#include <cuda_runtime.h>
#include <math.h>
#include <stdint.h>

#define SLICE 32768      // 512*64 floats per (b,f) slice
#define HALF  16384      // per-rank half of a slice
#define M_HALF 256
#define NTHREADS 512
#define NSLICES 64       // B*C = 4*16

__device__ float g_bufs[(size_t)NSLICES * 5 * SLICE];
__device__ float g_acc[(size_t)NSLICES * SLICE];

// Dynamic shared memory
struct SmemT {
    float As[2][16][M_HALF];  // A staging, double-buffered          (32 KB)
    float Bs[2][16][64];      // spatial B staging                   (8 KB)
    float Lt[64][64];         // persistent temporal operator        (16 KB)
    float acc[M_HALF * 64];   // accumulator, my half                (64 KB)
};                            // total 120 KB

#define CLUSTER_SYNC() do { \
    asm volatile("barrier.cluster.arrive.aligned;" ::: "memory"); \
    asm volatile("barrier.cluster.wait.aligned;" ::: "memory"); \
} while (0)

__device__ __forceinline__ uint32_t smem_u32(const void* p) {
    uint32_t a;
    asm("{ .reg .u64 t; cvta.to.shared.u64 t, %1; cvt.u32.u64 %0, t; }" : "=r"(a) : "l"(p));
    return a;
}

__device__ __forceinline__ void mbar_init(uint32_t addr, uint32_t cnt) {
    asm volatile("mbarrier.init.shared.b64 [%0], %1;" :: "r"(addr), "r"(cnt) : "memory");
}

__device__ __forceinline__ void st_peer_f32(uint32_t local_addr, uint32_t peer, float v) {
    uint32_t ra;
    asm volatile("mapa.shared::cluster.u32 %0, %1, %2;" : "=r"(ra) : "r"(local_addr), "r"(peer));
    asm volatile("st.shared::cluster.f32 [%0], %1;" :: "r"(ra), "f"(v) : "memory");
}

// release-arrive on the peer CTA's mbarrier (orders all my prior global/smem stores)
__device__ __forceinline__ void mbar_arrive_peer(uint32_t local_addr, uint32_t peer) {
    uint32_t ra;
    asm volatile("mapa.shared::cluster.u32 %0, %1, %2;" : "=r"(ra) : "r"(local_addr), "r"(peer));
    asm volatile("mbarrier.arrive.release.cluster.shared::cluster.b64 _, [%0];"
                 :: "r"(ra) : "memory");
}

__device__ __forceinline__ void mbar_wait(uint32_t mbar, uint32_t parity) {
    uint32_t done;
    asm volatile(
        "{\n\t.reg .pred p;\n\t"
        "mbarrier.try_wait.parity.acquire.cta.shared::cta.b64 p, [%1], %2;\n\t"
        "selp.b32 %0, 1, 0, p;\n\t}"
        : "=r"(done) : "r"(mbar), "r"(parity) : "memory");
    if (!done) {
        asm volatile(
            "{\n\t.reg .pred P1;\n\t"
            "WAIT_LOOP_%=:\n\t"
            "mbarrier.try_wait.parity.acquire.cta.shared::cta.b64 P1, [%0], %1, 0x989680;\n\t"
            "@P1 bra.uni WAIT_DONE_%=;\n\t"
            "bra.uni WAIT_LOOP_%=;\n\t"
            "WAIT_DONE_%=:\n\t}"
            :: "r"(mbar), "r"(parity) : "memory");
    }
}

// ---------------- fused 3-value reduction: ONE barrier ----------------
// All threads end up with the block-wide sums (redundant 16-way add, broadcast LDS).
__device__ __forceinline__ void reduce3(float& a, float& b, float& c,
                                        float* red, int par, int tid) {
    #pragma unroll
    for (int o = 16; o; o >>= 1) {
        a += __shfl_xor_sync(0xffffffffu, a, o);
        b += __shfl_xor_sync(0xffffffffu, b, o);
        c += __shfl_xor_sync(0xffffffffu, c, o);
    }
    int w = tid >> 5, l = tid & 31;
    if (l == 0) *(float4*)&red[par * 64 + w * 4] = make_float4(a, b, c, 0.f);
    __syncthreads();
    float sa = 0.f, sb = 0.f, sc = 0.f;
    #pragma unroll
    for (int w2 = 0; w2 < 16; w2++) {
        float4 v = *(const float4*)&red[par * 64 + w2 * 4];
        sa += v.x; sb += v.y; sc += v.z;
    }
    a = sa; b = sb; c = sc;
}

// ---------------- one basis step (per-rank half of the M dimension) ----------------
// rst = A @ B (my 256 rows); analytic-norm Gram-Schmidt epilogue; sm->acc += th*dst.
template<bool SPATIAL>
__device__ void basis_step(const float* __restrict__ A,
                           const float* __restrict__ Bg,   // spatial B (global); temporal uses sm->Lt
                           float* __restrict__ dsth,
                           const float* __restrict__ lasth,
                           const float* __restrict__ sech,
                           float th, SmemT* sm, float* red,
                           float* xch, uint32_t xch_addr,
                           uint32_t bar0, uint32_t bar1, uint32_t peer,
                           int slot, int parity)
{
    constexpr int K = SPATIAL ? 512 : 64;
    constexpr int LDA = SPATIAL ? 512 : 64;
    constexpr int TILES = K / 16;

    const int tid = threadIdx.x;
    const int rl  = tid >> 1;          // staging row 0..255 (warp w covers rows 16w..16w+15)
    const int kh  = (tid & 1) * 8;     // which 8 of 16 k's this thread stages
    const int n0  = (tid >> 3) * 4;    // 4-row group (warp w covers rows 16w..16w+15)
    const int t0  = (tid & 7) * 8;     // 8-col group
    const bool has_sec = (sech != nullptr);

    float av[4][8];
    #pragma unroll
    for (int i = 0; i < 4; i++)
        #pragma unroll
        for (int j = 0; j < 8; j++) av[i][j] = 0.f;

    // ---- prologue: stage tile 0 ----
    {
        const float* ar = A + (size_t)rl * LDA + kh;
        float4 a0 = *(const float4*)(ar);
        float4 a1 = *(const float4*)(ar + 4);
        sm->As[0][kh + 0][rl] = a0.x; sm->As[0][kh + 1][rl] = a0.y;
        sm->As[0][kh + 2][rl] = a0.z; sm->As[0][kh + 3][rl] = a0.w;
        sm->As[0][kh + 4][rl] = a1.x; sm->As[0][kh + 5][rl] = a1.y;
        sm->As[0][kh + 6][rl] = a1.z; sm->As[0][kh + 7][rl] = a1.w;
        if (SPATIAL && tid < 256)
            ((float4*)&sm->Bs[0][0][0])[tid] = __ldcg((const float4*)Bg + tid);
    }
    __syncthreads();

    int p = 0;
    for (int t = 0; t < TILES; t++) {
        float4 na0, na1, nbv;
        const bool more = (t + 1 < TILES);
        if (more) {
            const int kt = (t + 1) * 16;
            const float* ar = A + (size_t)rl * LDA + kt + kh;
            na0 = *(const float4*)(ar);
            na1 = *(const float4*)(ar + 4);
            if (SPATIAL && tid < 256)
                nbv = __ldcg((const float4*)(Bg + (size_t)kt * 64) + tid);
        }

        const int ktb = t * 16;
        #pragma unroll
        for (int k = 0; k < 16; k++) {
            float4 aa = *(const float4*)&sm->As[p][k][n0];
            const float* brow = SPATIAL ? &sm->Bs[p][k][t0] : &sm->Lt[ktb + k][t0];
            float4 b0 = *(const float4*)brow;
            float4 b1 = *(const float4*)(brow + 4);
            float a[4] = {aa.x, aa.y, aa.z, aa.w};
            float b[8] = {b0.x, b0.y, b0.z, b0.w, b1.x, b1.y, b1.z, b1.w};
            #pragma unroll
            for (int i = 0; i < 4; i++)
                #pragma unroll
                for (int j = 0; j < 8; j++)
                    av[i][j] = fmaf(a[i], b[j], av[i][j]);
        }

        if (more) {
            const int q = p ^ 1;
            sm->As[q][kh + 0][rl] = na0.x; sm->As[q][kh + 1][rl] = na0.y;
            sm->As[q][kh + 2][rl] = na0.z; sm->As[q][kh + 3][rl] = na0.w;
            sm->As[q][kh + 4][rl] = na1.x; sm->As[q][kh + 5][rl] = na1.y;
            sm->As[q][kh + 6][rl] = na1.z; sm->As[q][kh + 7][rl] = na1.w;
            if (SPATIAL && tid < 256) ((float4*)&sm->Bs[q][0][0])[tid] = nbv;
            __syncthreads();
            p = q;
        }
    }

    // ---- partial dots + norm from registers ----
    float pd1 = 0.f, pd2 = 0.f, pr2 = 0.f;
    float4 lv[4][2];
    #pragma unroll
    for (int i = 0; i < 4; i++) {
        size_t base = (size_t)(n0 + i) * 64 + t0;
        lv[i][0] = *(const float4*)(lasth + base);
        lv[i][1] = *(const float4*)(lasth + base + 4);
        const float* lp = (const float*)&lv[i][0];
        #pragma unroll
        for (int j = 0; j < 8; j++) {
            pd1 = fmaf(av[i][j], lp[j], pd1);
            pr2 = fmaf(av[i][j], av[i][j], pr2);
        }
        if (has_sec) {
            float4 s0 = *(const float4*)(sech + base);
            float4 s1 = *(const float4*)(sech + base + 4);
            float s[8] = {s0.x, s0.y, s0.z, s0.w, s1.x, s1.y, s1.z, s1.w};
            #pragma unroll
            for (int j = 0; j < 8; j++) pd2 = fmaf(av[i][j], s[j], pd2);
        }
    }
    reduce3(pd1, pd2, pr2, red, slot, tid);

    // ---- cross-CTA scalar exchange: push to peer + mbarrier handshake ----
    const uint32_t bar = slot ? bar1 : bar0;
    if (tid == 0) {
        st_peer_f32(xch_addr + (4 * slot + 0) * 4, peer, pd1);
        st_peer_f32(xch_addr + (4 * slot + 1) * 4, peer, pd2);
        st_peer_f32(xch_addr + (4 * slot + 2) * 4, peer, pr2);
        mbar_arrive_peer(bar, peer);
    }
    mbar_wait(bar, (uint32_t)parity);
    float d1 = pd1 + xch[4 * slot + 0];
    float d2 = has_sec ? (pd2 + xch[4 * slot + 1]) : 0.f;
    float r2 = pr2 + xch[4 * slot + 2];
    float n2 = r2 - d1 * d1 - d2 * d2;
    float inv = 1.f / fmaxf(sqrtf(fmaxf(n2, 0.f)), 1e-8f);

    // ---- write normalized dst (global) + acc update (smem) ----
    float* accs = sm->acc;
    #pragma unroll
    for (int i = 0; i < 4; i++) {
        size_t base = (size_t)(n0 + i) * 64 + t0;
        const float* lp = (const float*)&lv[i][0];
        float v[8];
        if (has_sec) {
            float4 s0 = *(const float4*)(sech + base);
            float4 s1 = *(const float4*)(sech + base + 4);
            float s[8] = {s0.x, s0.y, s0.z, s0.w, s1.x, s1.y, s1.z, s1.w};
            #pragma unroll
            for (int j = 0; j < 8; j++) v[j] = (av[i][j] - d1 * lp[j] - d2 * s[j]) * inv;
        } else {
            #pragma unroll
            for (int j = 0; j < 8; j++) v[j] = (av[i][j] - d1 * lp[j]) * inv;
        }
        *(float4*)(dsth + base)     = make_float4(v[0], v[1], v[2], v[3]);
        *(float4*)(dsth + base + 4) = make_float4(v[4], v[5], v[6], v[7]);
        float4 a0 = *(float4*)(accs + base);
        float4 a1 = *(float4*)(accs + base + 4);
        a0.x = fmaf(th, v[0], a0.x); a0.y = fmaf(th, v[1], a0.y);
        a0.z = fmaf(th, v[2], a0.z); a0.w = fmaf(th, v[3], a0.w);
        a1.x = fmaf(th, v[4], a1.x); a1.y = fmaf(th, v[5], a1.y);
        a1.z = fmaf(th, v[6], a1.z); a1.w = fmaf(th, v[7], a1.w);
        *(float4*)(accs + base)     = a0;
        *(float4*)(accs + base + 4) = a1;
    }
}

// ---------------- main kernel: 2-CTA cluster per (b,f) slice ----------------
__global__ void __cluster_dims__(2, 1, 1) __launch_bounds__(NTHREADS, 1)
st_main_kernel(const float* __restrict__ x,
               const float* __restrict__ Ls,
               const float* __restrict__ Lt,
               const float* __restrict__ STE,
               const float* __restrict__ w_t1, const float* __restrict__ b_t1,
               const float* __restrict__ w_t2, const float* __restrict__ b_t2)
{
    extern __shared__ __align__(16) char smem_raw[];
    SmemT* sm = reinterpret_cast<SmemT*>(smem_raw);

    __shared__ __align__(16) float red[2 * 64];
    __shared__ float theta_sm[66];
    __shared__ float h1_sm[60];
    __shared__ __align__(16) float xch[8];
    __shared__ __align__(8) unsigned long long mbars[2];

    const int tid = threadIdx.x;
    const int slice = blockIdx.x >> 1;
    const uint32_t rank = blockIdx.x & 1;
    const uint32_t peer = rank ^ 1;
    const int b = slice >> 4;
    const uint32_t xch_addr = smem_u32(xch);
    const uint32_t bar0 = smem_u32(&mbars[0]);
    const uint32_t bar1 = smem_u32(&mbars[1]);
    const size_t hoff = (size_t)rank * HALF;

    const float* xs = x + (size_t)slice * SLICE;
    float* accg = g_acc + (size_t)slice * SLICE;
    float* bufp[5];
    #pragma unroll
    for (int i = 0; i < 5; i++) bufp[i] = g_bufs + ((size_t)slice * 5 + i) * SLICE;

    // ---- init mbarriers, load Lt, theta MLP ----
    if (tid == 0) { mbar_init(bar0, 1); mbar_init(bar1, 1); }
    for (int i = tid; i < 64 * 64 / 4; i += NTHREADS)
        ((float4*)&sm->Lt[0][0])[i] = ((const float4*)Lt)[i];

    if (tid < 60) {
        int o = tid / 10, s = tid % 10;
        float h = b_t1[o];
        #pragma unroll
        for (int t = 0; t < 5; t++) h = fmaf(w_t1[o * 5 + t], STE[b * 50 + t * 10 + s], h);
        h1_sm[o * 10 + s] = h;
    }
    __syncthreads();
    if (tid < 66) {
        int p = tid % 11, o = tid / 11;
        float h = b_t2[p];
        #pragma unroll
        for (int s = 0; s < 10; s++) h = fmaf(w_t2[p * 10 + s], h1_sm[o * 10 + s], h);
        theta_sm[o * 11 + p] = fmaxf(h, 0.f);   // flat r = o*11 + p matches M order
    }
    CLUSTER_SYNC();   // mbarrier init visible cluster-wide before first arrive

    int par01[2] = {0, 0};

    // ---- step 0: m00 = x / fro(x);  acc = theta[0] * m00  (my half) ----
    float pnv = 0.f, z1 = 0.f, z2 = 0.f;
    const float4* x4 = (const float4*)(xs + hoff);
    for (int i = tid; i < HALF / 4; i += NTHREADS) {
        float4 v = x4[i];
        pnv += v.x * v.x + v.y * v.y + v.z * v.z + v.w * v.w;
    }
    reduce3(pnv, z1, z2, red, 0, tid);
    if (tid == 0) {
        st_peer_f32(xch_addr + 0, peer, pnv);
        st_peer_f32(xch_addr + 4, peer, 0.f);
        st_peer_f32(xch_addr + 8, peer, 0.f);
        mbar_arrive_peer(bar0, peer);
    }
    mbar_wait(bar0, 0);
    par01[0] ^= 1;
    float nv = pnv + xch[0];
    float inv = 1.f / fmaxf(sqrtf(nv), 1e-8f);
    float th0 = theta_sm[0];
    float4* b04 = (float4*)(bufp[0] + hoff);
    float4* a4 = (float4*)sm->acc;
    for (int i = tid; i < HALF / 4; i += NTHREADS) {
        float4 v = x4[i];
        v.x *= inv; v.y *= inv; v.z *= inv; v.w *= inv;
        b04[i] = v;
        a4[i] = make_float4(th0 * v.x, th0 * v.y, th0 * v.z, th0 * v.w);
    }
    __syncthreads();   // bufp[0]/acc half complete before step 1 staging

    // ---- recurrence ----
    int last_s = 0, sec_s = -1, last_t = 0, sec_t = -1;
    int r = 1;
    int step = 1;
    for (int i = 0; i <= 10; i++) {
        if (i > 0) {
            int nb = 0;
            while (nb == last_s || nb == sec_s || nb == last_t || nb == sec_t) nb++;
            int slot = step & 1;
            basis_step<true>(Ls + (size_t)rank * M_HALF * 512,
                             bufp[last_s],
                             bufp[nb] + hoff,
                             bufp[last_s] + hoff,
                             (sec_s >= 0) ? bufp[sec_s] + hoff : nullptr,
                             theta_sm[r], sm, red, xch, xch_addr,
                             bar0, bar1, peer, slot, par01[slot]);
            par01[slot] ^= 1;
            sec_s = last_s; last_s = nb;
            last_t = nb; sec_t = -1;
            r++; step++;
        }
        for (int j = 0; j < 5; j++) {
            int nb = 0;
            while (nb == last_s || nb == sec_s || nb == last_t || nb == sec_t) nb++;
            int slot = step & 1;
            basis_step<false>(bufp[last_t] + hoff,
                              nullptr,
                              bufp[nb] + hoff,
                              bufp[last_t] + hoff,
                              (sec_t >= 0) ? bufp[sec_t] + hoff : nullptr,
                              theta_sm[r], sm, red, xch, xch_addr,
                              bar0, bar1, peer, slot, par01[slot]);
            par01[slot] ^= 1;
            sec_t = last_t; last_t = nb;
            r++; step++;
        }
    }

    // ---- write accumulated x_st back to global ----
    __syncthreads();
    float4* ag4 = (float4*)(accg + hoff);
    const float4* as4 = (const float4*)sm->acc;
    for (int i = tid; i < HALF / 4; i += NTHREADS) ag4[i] = as4[i];
}

// ---------------- output MLP + folded BatchNorm ----------------
__global__ __launch_bounds__(256)
void st_out_kernel(const float* __restrict__ x,
                   const float* __restrict__ w_mlp, const float* __restrict__ b_mlp,
                   const float* __restrict__ gamma, const float* __restrict__ beta,
                   const float* __restrict__ mean, const float* __restrict__ var,
                   float* __restrict__ out)
{
    __shared__ float ws[64][32];
    __shared__ float bs[64];
    const int tid = threadIdx.x;
    for (int i = tid; i < 64 * 32; i += 256) {
        int o = i >> 5;
        float invs = gamma[o] * rsqrtf(var[o] + 1e-5f);
        ws[o][i & 31] = w_mlp[i] * invs;
    }
    if (tid < 64) {
        float invs = gamma[tid] * rsqrtf(var[tid] + 1e-5f);
        bs[tid] = b_mlp[tid] * invs + beta[tid] - mean[tid] * invs;
    }
    __syncthreads();

    const int b = blockIdx.y;
    const int pt = blockIdx.x * 256 + tid;   // 0..32767

    float xv[16], av[16];
    #pragma unroll
    for (int c = 0; c < 16; c++) {
        xv[c] = x[((size_t)(b * 16 + c)) * SLICE + pt];
        av[c] = g_acc[((size_t)(b * 16 + c)) * SLICE + pt];
    }
    #pragma unroll
    for (int o = 0; o < 64; o++) {
        float s = bs[o];
        #pragma unroll
        for (int c = 0; c < 16; c++) {
            s = fmaf(ws[o][c], xv[c], s);
            s = fmaf(ws[o][16 + c], av[c], s);
        }
        out[((size_t)(b * 64 + o)) * SLICE + pt] = s;
    }
}

extern "C" void kernel_launch(void* const* d_in, const int* in_sizes, int n_in,
                              void* d_out, int out_size) {
    const float* x    = (const float*)d_in[0];
    const float* Ls   = (const float*)d_in[1];
    const float* Lt   = (const float*)d_in[2];
    const float* STE  = (const float*)d_in[3];
    const float* w_t1 = (const float*)d_in[4];
    const float* b_t1 = (const float*)d_in[5];
    const float* w_t2 = (const float*)d_in[6];
    const float* b_t2 = (const float*)d_in[7];
    const float* w_mlp = (const float*)d_in[8];
    const float* b_mlp = (const float*)d_in[9];
    const float* gamma = (const float*)d_in[10];
    const float* beta  = (const float*)d_in[11];
    const float* mean  = (const float*)d_in[12];
    const float* var   = (const float*)d_in[13];
    float* out = (float*)d_out;

    cudaFuncSetAttribute(st_main_kernel,
                         cudaFuncAttributeMaxDynamicSharedMemorySize, (int)sizeof(SmemT));
    st_main_kernel<<<NSLICES * 2, NTHREADS, sizeof(SmemT)>>>(
        x, Ls, Lt, STE, w_t1, b_t1, w_t2, b_t2);
    st_out_kernel<<<dim3(128, 4), 256>>>(x, w_mlp, b_mlp, gamma, beta, mean, var, out);
}

// round 9
// speedup vs baseline: 1.3321x; 1.1141x over previous
#include <cuda_runtime.h>
#include <math.h>
#include <stdint.h>

#define SLICE 32768      // 512*64 floats per (b,f) slice
#define HALF  16384      // per-rank half of a slice
#define M_HALF 256
#define NTHREADS 512
#define NSLICES 64       // B*C = 4*16

__device__ float g_bufs[(size_t)NSLICES * 3 * SLICE];   // spatial chain (global, 3 rotating)
__device__ float g_acc[(size_t)NSLICES * SLICE];

// T buffers: transposed [t][n_half] float4 tiles with XOR swizzle (bank-spread)
#define SW(t, n4) (((t) << 6) + ((n4) ^ (((t) >> 3) & 7)))

struct SmemT {
    float4 T[3][4096];    // 3 x 64 KB temporal-chain buffers (T[1] aliased by As/Bs in spatial steps)
    float  Lt[64][64];    // persistent temporal operator (16 KB)
};                        // 208 KB dynamic

#define CLUSTER_SYNC() do { \
    asm volatile("barrier.cluster.arrive.aligned;" ::: "memory"); \
    asm volatile("barrier.cluster.wait.aligned;" ::: "memory"); \
} while (0)

__device__ __forceinline__ uint32_t smem_u32(const void* p) {
    uint32_t a;
    asm("{ .reg .u64 t; cvta.to.shared.u64 t, %1; cvt.u32.u64 %0, t; }" : "=r"(a) : "l"(p));
    return a;
}
__device__ __forceinline__ void mbar_init(uint32_t addr, uint32_t cnt) {
    asm volatile("mbarrier.init.shared.b64 [%0], %1;" :: "r"(addr), "r"(cnt) : "memory");
}
__device__ __forceinline__ void st_peer_f32(uint32_t local_addr, uint32_t peer, float v) {
    uint32_t ra;
    asm volatile("mapa.shared::cluster.u32 %0, %1, %2;" : "=r"(ra) : "r"(local_addr), "r"(peer));
    asm volatile("st.shared::cluster.f32 [%0], %1;" :: "r"(ra), "f"(v) : "memory");
}
__device__ __forceinline__ void mbar_arrive_peer(uint32_t local_addr, uint32_t peer) {
    uint32_t ra;
    asm volatile("mapa.shared::cluster.u32 %0, %1, %2;" : "=r"(ra) : "r"(local_addr), "r"(peer));
    asm volatile("mbarrier.arrive.release.cluster.shared::cluster.b64 _, [%0];"
                 :: "r"(ra) : "memory");
}
__device__ __forceinline__ void mbar_wait(uint32_t mbar, uint32_t parity) {
    uint32_t done;
    asm volatile(
        "{\n\t.reg .pred p;\n\t"
        "mbarrier.try_wait.parity.acquire.cta.shared::cta.b64 p, [%1], %2;\n\t"
        "selp.b32 %0, 1, 0, p;\n\t}"
        : "=r"(done) : "r"(mbar), "r"(parity) : "memory");
    if (!done) {
        asm volatile(
            "{\n\t.reg .pred P1;\n\t"
            "WAIT_LOOP_%=:\n\t"
            "mbarrier.try_wait.parity.acquire.cta.shared::cta.b64 P1, [%0], %1, 0x989680;\n\t"
            "@P1 bra.uni WAIT_DONE_%=;\n\t"
            "bra.uni WAIT_LOOP_%=;\n\t"
            "WAIT_DONE_%=:\n\t}"
            :: "r"(mbar), "r"(parity) : "memory");
    }
}

// ---------------- fused 3-value reduction: ONE barrier ----------------
__device__ __forceinline__ void reduce3(float& a, float& b, float& c,
                                        float* red, int slot, int tid) {
    #pragma unroll
    for (int o = 16; o; o >>= 1) {
        a += __shfl_xor_sync(0xffffffffu, a, o);
        b += __shfl_xor_sync(0xffffffffu, b, o);
        c += __shfl_xor_sync(0xffffffffu, c, o);
    }
    int w = tid >> 5, l = tid & 31;
    if (l == 0) *(float4*)&red[slot * 64 + w * 4] = make_float4(a, b, c, 0.f);
    __syncthreads();
    float sa = 0.f, sb = 0.f, sc = 0.f;
    #pragma unroll
    for (int w2 = 0; w2 < 16; w2++) {
        float4 v = *(const float4*)&red[slot * 64 + w2 * 4];
        sa += v.x; sb += v.y; sc += v.z;
    }
    a = sa; b = sb; c = sc;
}

// cross-CTA scalar exchange + compute d1,d2,inv  (R7-proven handshake)
__device__ __forceinline__ void exchange3(float pd1, float pd2, float pr2, bool has_sec,
                                          float* xch, uint32_t xch_addr,
                                          uint32_t bar0, uint32_t bar1, uint32_t peer,
                                          int slot, int parity,
                                          float& d1, float& d2, float& inv, int tid) {
    const uint32_t bar = slot ? bar1 : bar0;
    if (tid == 0) {
        st_peer_f32(xch_addr + (4 * slot + 0) * 4, peer, pd1);
        st_peer_f32(xch_addr + (4 * slot + 1) * 4, peer, pd2);
        st_peer_f32(xch_addr + (4 * slot + 2) * 4, peer, pr2);
        mbar_arrive_peer(bar, peer);
    }
    mbar_wait(bar, (uint32_t)parity);
    d1 = pd1 + xch[4 * slot + 0];
    d2 = has_sec ? (pd2 + xch[4 * slot + 1]) : 0.f;
    float r2 = pr2 + xch[4 * slot + 2];
    float n2 = r2 - d1 * d1 - d2 * d2;
    inv = 1.f / fmaxf(sqrtf(fmaxf(n2, 0.f)), 1e-8f);
}

// ---------------- temporal basis step: all-smem, no staging ----------------
__device__ __forceinline__ void basis_step_t(
    const float4* __restrict__ Tl, const float4* __restrict__ Ts,
    float4* __restrict__ Tn, const float (*Lts)[64],
    float th, float (&accv)[4][8],
    float* red, float* xch, uint32_t xch_addr,
    uint32_t bar0, uint32_t bar1, uint32_t peer, int slot, int parity)
{
    const int tid = threadIdx.x;
    const int n4 = tid >> 3;
    const int t0 = (tid & 7) * 8;
    const bool has_sec = (Ts != nullptr);

    float av[4][8];
    #pragma unroll
    for (int i = 0; i < 4; i++)
        #pragma unroll
        for (int j = 0; j < 8; j++) av[i][j] = 0.f;

    #pragma unroll 8
    for (int k = 0; k < 64; k++) {
        float4 a  = Tl[SW(k, n4)];
        float4 b0 = *(const float4*)&Lts[k][t0];
        float4 b1 = *(const float4*)&Lts[k][t0 + 4];
        float aa[4] = {a.x, a.y, a.z, a.w};
        float bb[8] = {b0.x, b0.y, b0.z, b0.w, b1.x, b1.y, b1.z, b1.w};
        #pragma unroll
        for (int i = 0; i < 4; i++)
            #pragma unroll
            for (int j = 0; j < 8; j++)
                av[i][j] = fmaf(aa[i], bb[j], av[i][j]);
    }

    float pd1 = 0.f, pd2 = 0.f, pr2 = 0.f;
    #pragma unroll
    for (int j = 0; j < 8; j++) {
        float4 l = Tl[SW(t0 + j, n4)];
        pd1 += av[0][j] * l.x + av[1][j] * l.y + av[2][j] * l.z + av[3][j] * l.w;
    }
    #pragma unroll
    for (int i = 0; i < 4; i++)
        #pragma unroll
        for (int j = 0; j < 8; j++) pr2 = fmaf(av[i][j], av[i][j], pr2);
    if (has_sec) {
        #pragma unroll
        for (int j = 0; j < 8; j++) {
            float4 s = Ts[SW(t0 + j, n4)];
            pd2 += av[0][j] * s.x + av[1][j] * s.y + av[2][j] * s.z + av[3][j] * s.w;
        }
    }
    reduce3(pd1, pd2, pr2, red, slot, tid);
    float d1, d2, inv;
    exchange3(pd1, pd2, pr2, has_sec, xch, xch_addr, bar0, bar1, peer, slot, parity,
              d1, d2, inv, tid);

    #pragma unroll
    for (int j = 0; j < 8; j++) {
        float4 l = Tl[SW(t0 + j, n4)];
        float4 v;
        v.x = av[0][j] - d1 * l.x;
        v.y = av[1][j] - d1 * l.y;
        v.z = av[2][j] - d1 * l.z;
        v.w = av[3][j] - d1 * l.w;
        if (has_sec) {
            float4 s = Ts[SW(t0 + j, n4)];
            v.x -= d2 * s.x; v.y -= d2 * s.y; v.z -= d2 * s.z; v.w -= d2 * s.w;
        }
        v.x *= inv; v.y *= inv; v.z *= inv; v.w *= inv;
        Tn[SW(t0 + j, n4)] = v;
        accv[0][j] = fmaf(th, v.x, accv[0][j]);
        accv[1][j] = fmaf(th, v.y, accv[1][j]);
        accv[2][j] = fmaf(th, v.z, accv[2][j]);
        accv[3][j] = fmaf(th, v.w, accv[3][j]);
    }
    __syncthreads();
}

// ---------------- spatial basis step: global A/B, dst -> global + T0 ----------------
__device__ __forceinline__ void basis_step_s(
    const float* __restrict__ A,        // my 256 rows of Ls
    const float* __restrict__ Bg,       // full last_s buffer (global)
    float* __restrict__ dstg,           // my half of new spatial buffer (global)
    const float* __restrict__ lasth,    // my half of last_s
    const float* __restrict__ sech,     // my half of sec_s (or null)
    float4* __restrict__ Tn,            // T[0] (temporal chain restart)
    float th, float (&accv)[4][8],
    SmemT* sm, float* red, float* xch, uint32_t xch_addr,
    uint32_t bar0, uint32_t bar1, uint32_t peer, int slot, int parity)
{
    // As/Bs staging aliases T[1] (dead during spatial steps)
    float (*As)[16][M_HALF] = (float (*)[16][M_HALF])(&sm->T[1][0]);
    float (*Bs)[16][64]     = (float (*)[16][64])((float*)&sm->T[1][0] + 8192);

    const int tid = threadIdx.x;
    const int rl  = tid >> 1;
    const int kh  = (tid & 1) * 8;
    const int n4  = tid >> 3;
    const int n0  = n4 * 4;
    const int t0  = (tid & 7) * 8;
    const bool has_sec = (sech != nullptr);

    float av[4][8];
    #pragma unroll
    for (int i = 0; i < 4; i++)
        #pragma unroll
        for (int j = 0; j < 8; j++) av[i][j] = 0.f;

    // prologue: stage tile 0
    {
        const float* ar = A + (size_t)rl * 512 + kh;
        float4 a0 = *(const float4*)(ar);
        float4 a1 = *(const float4*)(ar + 4);
        As[0][kh + 0][rl] = a0.x; As[0][kh + 1][rl] = a0.y;
        As[0][kh + 2][rl] = a0.z; As[0][kh + 3][rl] = a0.w;
        As[0][kh + 4][rl] = a1.x; As[0][kh + 5][rl] = a1.y;
        As[0][kh + 6][rl] = a1.z; As[0][kh + 7][rl] = a1.w;
        if (tid < 256)
            ((float4*)&Bs[0][0][0])[tid] = __ldcg((const float4*)Bg + tid);
    }
    __syncthreads();

    int p = 0;
    for (int t = 0; t < 32; t++) {
        float4 na0, na1, nbv;
        const bool more = (t + 1 < 32);
        if (more) {
            const int kt = (t + 1) * 16;
            const float* ar = A + (size_t)rl * 512 + kt + kh;
            na0 = *(const float4*)(ar);
            na1 = *(const float4*)(ar + 4);
            if (tid < 256)
                nbv = __ldcg((const float4*)(Bg + (size_t)kt * 64) + tid);
        }
        #pragma unroll
        for (int k = 0; k < 16; k++) {
            float4 aa = *(const float4*)&As[p][k][n0];
            float4 b0 = *(const float4*)&Bs[p][k][t0];
            float4 b1 = *(const float4*)&Bs[p][k][t0 + 4];
            float a[4] = {aa.x, aa.y, aa.z, aa.w};
            float b[8] = {b0.x, b0.y, b0.z, b0.w, b1.x, b1.y, b1.z, b1.w};
            #pragma unroll
            for (int i = 0; i < 4; i++)
                #pragma unroll
                for (int j = 0; j < 8; j++)
                    av[i][j] = fmaf(a[i], b[j], av[i][j]);
        }
        if (more) {
            const int q = p ^ 1;
            As[q][kh + 0][rl] = na0.x; As[q][kh + 1][rl] = na0.y;
            As[q][kh + 2][rl] = na0.z; As[q][kh + 3][rl] = na0.w;
            As[q][kh + 4][rl] = na1.x; As[q][kh + 5][rl] = na1.y;
            As[q][kh + 6][rl] = na1.z; As[q][kh + 7][rl] = na1.w;
            if (tid < 256) ((float4*)&Bs[q][0][0])[tid] = nbv;
            __syncthreads();
            p = q;
        }
    }

    // dots + norm
    float pd1 = 0.f, pd2 = 0.f, pr2 = 0.f;
    #pragma unroll
    for (int i = 0; i < 4; i++) {
        int base = (n0 + i) * 64 + t0;
        float4 l0 = *(const float4*)(lasth + base);
        float4 l1 = *(const float4*)(lasth + base + 4);
        float lp[8] = {l0.x, l0.y, l0.z, l0.w, l1.x, l1.y, l1.z, l1.w};
        #pragma unroll
        for (int j = 0; j < 8; j++) {
            pd1 = fmaf(av[i][j], lp[j], pd1);
            pr2 = fmaf(av[i][j], av[i][j], pr2);
        }
        if (has_sec) {
            float4 s0 = *(const float4*)(sech + base);
            float4 s1 = *(const float4*)(sech + base + 4);
            float sp[8] = {s0.x, s0.y, s0.z, s0.w, s1.x, s1.y, s1.z, s1.w};
            #pragma unroll
            for (int j = 0; j < 8; j++) pd2 = fmaf(av[i][j], sp[j], pd2);
        }
    }
    reduce3(pd1, pd2, pr2, red, slot, tid);
    float d1, d2, inv;
    exchange3(pd1, pd2, pr2, has_sec, xch, xch_addr, bar0, bar1, peer, slot, parity,
              d1, d2, inv, tid);

    // write: global rows + transposed T0 + acc regs
    float v[4][8];
    #pragma unroll
    for (int i = 0; i < 4; i++) {
        int base = (n0 + i) * 64 + t0;
        float4 l0 = *(const float4*)(lasth + base);
        float4 l1 = *(const float4*)(lasth + base + 4);
        float lp[8] = {l0.x, l0.y, l0.z, l0.w, l1.x, l1.y, l1.z, l1.w};
        #pragma unroll
        for (int j = 0; j < 8; j++) v[i][j] = av[i][j] - d1 * lp[j];
        if (has_sec) {
            float4 s0 = *(const float4*)(sech + base);
            float4 s1 = *(const float4*)(sech + base + 4);
            float sp[8] = {s0.x, s0.y, s0.z, s0.w, s1.x, s1.y, s1.z, s1.w};
            #pragma unroll
            for (int j = 0; j < 8; j++) v[i][j] -= d2 * sp[j];
        }
        #pragma unroll
        for (int j = 0; j < 8; j++) v[i][j] *= inv;
        *(float4*)(dstg + base)     = make_float4(v[i][0], v[i][1], v[i][2], v[i][3]);
        *(float4*)(dstg + base + 4) = make_float4(v[i][4], v[i][5], v[i][6], v[i][7]);
    }
    #pragma unroll
    for (int j = 0; j < 8; j++)
        Tn[SW(t0 + j, n4)] = make_float4(v[0][j], v[1][j], v[2][j], v[3][j]);
    #pragma unroll
    for (int i = 0; i < 4; i++)
        #pragma unroll
        for (int j = 0; j < 8; j++)
            accv[i][j] = fmaf(th, v[i][j], accv[i][j]);
    __syncthreads();
}

// ---------------- main kernel: 2-CTA cluster per (b,f) slice ----------------
__global__ void __cluster_dims__(2, 1, 1) __launch_bounds__(NTHREADS, 1)
st_main_kernel(const float* __restrict__ x,
               const float* __restrict__ Ls,
               const float* __restrict__ Lt,
               const float* __restrict__ STE,
               const float* __restrict__ w_t1, const float* __restrict__ b_t1,
               const float* __restrict__ w_t2, const float* __restrict__ b_t2)
{
    extern __shared__ __align__(16) char smem_raw[];
    SmemT* sm = reinterpret_cast<SmemT*>(smem_raw);

    __shared__ __align__(16) float red[2 * 64];
    __shared__ float theta_sm[66];
    __shared__ float h1_sm[60];
    __shared__ __align__(16) float xch[8];
    __shared__ __align__(8) unsigned long long mbars[2];

    const int tid = threadIdx.x;
    const int slice = blockIdx.x >> 1;
    const uint32_t rank = blockIdx.x & 1;
    const uint32_t peer = rank ^ 1;
    const int b = slice >> 4;
    const uint32_t xch_addr = smem_u32(xch);
    const uint32_t bar0 = smem_u32(&mbars[0]);
    const uint32_t bar1 = smem_u32(&mbars[1]);
    const size_t hoff = (size_t)rank * HALF;
    const int n4 = tid >> 3;
    const int n0 = n4 * 4;
    const int t0 = (tid & 7) * 8;

    const float* xs = x + (size_t)slice * SLICE;
    float* accg = g_acc + (size_t)slice * SLICE;
    float* bufp[3];
    #pragma unroll
    for (int i = 0; i < 3; i++) bufp[i] = g_bufs + ((size_t)slice * 3 + i) * SLICE;

    if (tid == 0) { mbar_init(bar0, 1); mbar_init(bar1, 1); }
    for (int i = tid; i < 64 * 64 / 4; i += NTHREADS)
        ((float4*)&sm->Lt[0][0])[i] = ((const float4*)Lt)[i];

    if (tid < 60) {
        int o = tid / 10, s = tid % 10;
        float h = b_t1[o];
        #pragma unroll
        for (int t = 0; t < 5; t++) h = fmaf(w_t1[o * 5 + t], STE[b * 50 + t * 10 + s], h);
        h1_sm[o * 10 + s] = h;
    }
    __syncthreads();
    if (tid < 66) {
        int p = tid % 11, o = tid / 11;
        float h = b_t2[p];
        #pragma unroll
        for (int s = 0; s < 10; s++) h = fmaf(w_t2[p * 10 + s], h1_sm[o * 10 + s], h);
        theta_sm[o * 11 + p] = fmaxf(h, 0.f);   // flat r = o*11 + p matches M order
    }
    CLUSTER_SYNC();   // mbarrier init visible cluster-wide before first arrive

    int par01[2] = {0, 0};
    float accv[4][8];

    // ---- step 0: m00 = x / fro(x), into global bufp[0] + T[0] + acc regs ----
    {
        const float* xh = xs + hoff;
        float pnv = 0.f, z1 = 0.f, z2 = 0.f;
        #pragma unroll
        for (int i = 0; i < 4; i++) {
            int base = (n0 + i) * 64 + t0;
            float4 x0 = *(const float4*)(xh + base);
            float4 x1 = *(const float4*)(xh + base + 4);
            pnv += x0.x * x0.x + x0.y * x0.y + x0.z * x0.z + x0.w * x0.w
                 + x1.x * x1.x + x1.y * x1.y + x1.z * x1.z + x1.w * x1.w;
        }
        reduce3(pnv, z1, z2, red, 0, tid);
        float d1, d2, invn;
        exchange3(pnv, 0.f, 0.f, false, xch, xch_addr, bar0, bar1, peer, 0, 0,
                  d1, d2, invn, tid);
        // exchange3 computes inv from r2-d1^2; for step0 we want plain 1/sqrt(sum)
        float nv = pnv + xch[0];
        float inv = 1.f / fmaxf(sqrtf(nv), 1e-8f);
        par01[0] ^= 1;
        float th0 = theta_sm[0];
        float* dst0 = bufp[0] + hoff;
        float v[4][8];
        #pragma unroll
        for (int i = 0; i < 4; i++) {
            int base = (n0 + i) * 64 + t0;
            float4 x0 = *(const float4*)(xh + base);
            float4 x1 = *(const float4*)(xh + base + 4);
            v[i][0] = x0.x * inv; v[i][1] = x0.y * inv; v[i][2] = x0.z * inv; v[i][3] = x0.w * inv;
            v[i][4] = x1.x * inv; v[i][5] = x1.y * inv; v[i][6] = x1.z * inv; v[i][7] = x1.w * inv;
            *(float4*)(dst0 + base)     = make_float4(v[i][0], v[i][1], v[i][2], v[i][3]);
            *(float4*)(dst0 + base + 4) = make_float4(v[i][4], v[i][5], v[i][6], v[i][7]);
            #pragma unroll
            for (int j = 0; j < 8; j++) accv[i][j] = th0 * v[i][j];
        }
        #pragma unroll
        for (int j = 0; j < 8; j++)
            sm->T[0][SW(t0 + j, n4)] = make_float4(v[0][j], v[1][j], v[2][j], v[3][j]);
        __syncthreads();
    }

    // ---- recurrence ----
    int last_s = 0, sec_s = -1;   // global spatial chain
    int lastT = 0, secT = -1;     // smem temporal chain
    int r = 1, step = 1;
    for (int i = 0; i <= 10; i++) {
        if (i > 0) {
            int nb = 0;
            while (nb == last_s || nb == sec_s) nb++;
            int slot = step & 1;
            basis_step_s(Ls + (size_t)rank * M_HALF * 512,
                         bufp[last_s],
                         bufp[nb] + hoff,
                         bufp[last_s] + hoff,
                         (sec_s >= 0) ? bufp[sec_s] + hoff : nullptr,
                         sm->T[0], theta_sm[r], accv,
                         sm, red, xch, xch_addr, bar0, bar1, peer, slot, par01[slot]);
            par01[slot] ^= 1;
            sec_s = last_s; last_s = nb;
            lastT = 0; secT = -1;
            r++; step++;
        }
        for (int j = 0; j < 5; j++) {
            int nT = 0;
            while (nT == lastT || nT == secT) nT++;
            int slot = step & 1;
            basis_step_t(sm->T[lastT],
                         (secT >= 0) ? sm->T[secT] : nullptr,
                         sm->T[nT], sm->Lt, theta_sm[r], accv,
                         red, xch, xch_addr, bar0, bar1, peer, slot, par01[slot]);
            par01[slot] ^= 1;
            secT = lastT; lastT = nT;
            r++; step++;
        }
    }

    // ---- write register accumulator to global ----
    float* ah = accg + hoff;
    #pragma unroll
    for (int i = 0; i < 4; i++) {
        int base = (n0 + i) * 64 + t0;
        *(float4*)(ah + base)     = make_float4(accv[i][0], accv[i][1], accv[i][2], accv[i][3]);
        *(float4*)(ah + base + 4) = make_float4(accv[i][4], accv[i][5], accv[i][6], accv[i][7]);
    }
}

// ---------------- output MLP + folded BatchNorm ----------------
__global__ __launch_bounds__(256)
void st_out_kernel(const float* __restrict__ x,
                   const float* __restrict__ w_mlp, const float* __restrict__ b_mlp,
                   const float* __restrict__ gamma, const float* __restrict__ beta,
                   const float* __restrict__ mean, const float* __restrict__ var,
                   float* __restrict__ out)
{
    __shared__ float ws[64][32];
    __shared__ float bs[64];
    const int tid = threadIdx.x;
    for (int i = tid; i < 64 * 32; i += 256) {
        int o = i >> 5;
        float invs = gamma[o] * rsqrtf(var[o] + 1e-5f);
        ws[o][i & 31] = w_mlp[i] * invs;
    }
    if (tid < 64) {
        float invs = gamma[tid] * rsqrtf(var[tid] + 1e-5f);
        bs[tid] = b_mlp[tid] * invs + beta[tid] - mean[tid] * invs;
    }
    __syncthreads();

    const int b = blockIdx.y;
    const int pt = blockIdx.x * 256 + tid;   // 0..32767

    float xv[16], av[16];
    #pragma unroll
    for (int c = 0; c < 16; c++) {
        xv[c] = x[((size_t)(b * 16 + c)) * SLICE + pt];
        av[c] = g_acc[((size_t)(b * 16 + c)) * SLICE + pt];
    }
    #pragma unroll
    for (int o = 0; o < 64; o++) {
        float s = bs[o];
        #pragma unroll
        for (int c = 0; c < 16; c++) {
            s = fmaf(ws[o][c], xv[c], s);
            s = fmaf(ws[o][16 + c], av[c], s);
        }
        out[((size_t)(b * 64 + o)) * SLICE + pt] = s;
    }
}

extern "C" void kernel_launch(void* const* d_in, const int* in_sizes, int n_in,
                              void* d_out, int out_size) {
    const float* x    = (const float*)d_in[0];
    const float* Ls   = (const float*)d_in[1];
    const float* Lt   = (const float*)d_in[2];
    const float* STE  = (const float*)d_in[3];
    const float* w_t1 = (const float*)d_in[4];
    const float* b_t1 = (const float*)d_in[5];
    const float* w_t2 = (const float*)d_in[6];
    const float* b_t2 = (const float*)d_in[7];
    const float* w_mlp = (const float*)d_in[8];
    const float* b_mlp = (const float*)d_in[9];
    const float* gamma = (const float*)d_in[10];
    const float* beta  = (const float*)d_in[11];
    const float* mean  = (const float*)d_in[12];
    const float* var   = (const float*)d_in[13];
    float* out = (float*)d_out;

    cudaFuncSetAttribute(st_main_kernel,
                         cudaFuncAttributeMaxDynamicSharedMemorySize, (int)sizeof(SmemT));
    st_main_kernel<<<NSLICES * 2, NTHREADS, sizeof(SmemT)>>>(
        x, Ls, Lt, STE, w_t1, b_t1, w_t2, b_t2);
    st_out_kernel<<<dim3(128, 4), 256>>>(x, w_mlp, b_mlp, gamma, beta, mean, var, out);
}

// round 13
// speedup vs baseline: 1.3338x; 1.0013x over previous
#include <cuda_runtime.h>
#include <math.h>
#include <stdint.h>

#define SLICE 32768      // 512*64 floats per (b,f) slice
#define HALF  16384      // per-rank half of a slice
#define M_HALF 256
#define NTHREADS 512
#define NSLICES 64       // B*C = 4*16

typedef unsigned long long ull;

__device__ float g_bufs[(size_t)NSLICES * 3 * SLICE];   // spatial chain (global, 3 rotating)
__device__ float g_acc[(size_t)NSLICES * SLICE];

// T buffers: transposed [t][n_half] float4 tiles with XOR swizzle (bank-spread)
#define SW(t, n4) (((t) << 6) + ((n4) ^ (((t) >> 3) & 7)))

struct SmemT {
    float4 T[3][4096];    // 3 x 64 KB temporal-chain buffers (T[1] aliased by As/Bs in spatial steps)
    float  Lt[64][64];    // persistent temporal operator (16 KB)
};                        // 208 KB dynamic

#define CLUSTER_SYNC() do { \
    asm volatile("barrier.cluster.arrive.aligned;" ::: "memory"); \
    asm volatile("barrier.cluster.wait.aligned;" ::: "memory"); \
} while (0)

__device__ __forceinline__ uint32_t smem_u32(const void* p) {
    uint32_t a;
    asm("{ .reg .u64 t; cvta.to.shared.u64 t, %1; cvt.u32.u64 %0, t; }" : "=r"(a) : "l"(p));
    return a;
}
__device__ __forceinline__ void mbar_init(uint32_t addr, uint32_t cnt) {
    asm volatile("mbarrier.init.shared.b64 [%0], %1;" :: "r"(addr), "r"(cnt) : "memory");
}
__device__ __forceinline__ void st_peer_f32(uint32_t local_addr, uint32_t peer, float v) {
    uint32_t ra;
    asm volatile("mapa.shared::cluster.u32 %0, %1, %2;" : "=r"(ra) : "r"(local_addr), "r"(peer));
    asm volatile("st.shared::cluster.f32 [%0], %1;" :: "r"(ra), "f"(v) : "memory");
}
__device__ __forceinline__ void mbar_arrive_peer(uint32_t local_addr, uint32_t peer) {
    uint32_t ra;
    asm volatile("mapa.shared::cluster.u32 %0, %1, %2;" : "=r"(ra) : "r"(local_addr), "r"(peer));
    asm volatile("mbarrier.arrive.release.cluster.shared::cluster.b64 _, [%0];"
                 :: "r"(ra) : "memory");
}
__device__ __forceinline__ void mbar_wait(uint32_t mbar, uint32_t parity) {
    uint32_t done;
    asm volatile(
        "{\n\t.reg .pred p;\n\t"
        "mbarrier.try_wait.parity.acquire.cta.shared::cta.b64 p, [%1], %2;\n\t"
        "selp.b32 %0, 1, 0, p;\n\t}"
        : "=r"(done) : "r"(mbar), "r"(parity) : "memory");
    if (!done) {
        asm volatile(
            "{\n\t.reg .pred P1;\n\t"
            "WAIT_LOOP_%=:\n\t"
            "mbarrier.try_wait.parity.acquire.cta.shared::cta.b64 P1, [%0], %1, 0x989680;\n\t"
            "@P1 bra.uni WAIT_DONE_%=;\n\t"
            "bra.uni WAIT_LOOP_%=;\n\t"
            "WAIT_DONE_%=:\n\t}"
            :: "r"(mbar), "r"(parity) : "memory");
    }
}

// ---------------- packed f32x2 helpers ----------------
__device__ __forceinline__ void fma2_acc(ull& d, ull a, ull b) {
    asm("fma.rn.f32x2 %0, %1, %2, %0;" : "+l"(d) : "l"(a), "l"(b));
}
__device__ __forceinline__ ull splat2(float x) {
    ull d;
    uint32_t u = __float_as_uint(x);
    asm("mov.b64 %0, {%1, %1};" : "=l"(d) : "r"(u));
    return d;
}
__device__ __forceinline__ float2 unpack2(ull v) {
    uint32_t lo, hi;
    asm("mov.b64 {%0, %1}, %2;" : "=r"(lo), "=r"(hi) : "l"(v));
    return make_float2(__uint_as_float(lo), __uint_as_float(hi));
}

// ---------------- fused 3-value reduction: ONE barrier ----------------
__device__ __forceinline__ void reduce3(float& a, float& b, float& c,
                                        float* red, int slot, int tid) {
    #pragma unroll
    for (int o = 16; o; o >>= 1) {
        a += __shfl_xor_sync(0xffffffffu, a, o);
        b += __shfl_xor_sync(0xffffffffu, b, o);
        c += __shfl_xor_sync(0xffffffffu, c, o);
    }
    int w = tid >> 5, l = tid & 31;
    if (l == 0) *(float4*)&red[slot * 64 + w * 4] = make_float4(a, b, c, 0.f);
    __syncthreads();
    float sa = 0.f, sb = 0.f, sc = 0.f;
    #pragma unroll
    for (int w2 = 0; w2 < 16; w2++) {
        float4 v = *(const float4*)&red[slot * 64 + w2 * 4];
        sa += v.x; sb += v.y; sc += v.z;
    }
    a = sa; b = sb; c = sc;
}

// cross-CTA scalar exchange + compute d1,d2,inv
__device__ __forceinline__ void exchange3(float pd1, float pd2, float pr2, bool has_sec,
                                          float* xch, uint32_t xch_addr,
                                          uint32_t bar0, uint32_t bar1, uint32_t peer,
                                          int slot, int parity,
                                          float& d1, float& d2, float& inv, int tid) {
    const uint32_t bar = slot ? bar1 : bar0;
    if (tid == 0) {
        st_peer_f32(xch_addr + (4 * slot + 0) * 4, peer, pd1);
        st_peer_f32(xch_addr + (4 * slot + 1) * 4, peer, pd2);
        st_peer_f32(xch_addr + (4 * slot + 2) * 4, peer, pr2);
        mbar_arrive_peer(bar, peer);
    }
    mbar_wait(bar, (uint32_t)parity);
    d1 = pd1 + xch[4 * slot + 0];
    d2 = has_sec ? (pd2 + xch[4 * slot + 1]) : 0.f;
    float r2 = pr2 + xch[4 * slot + 2];
    float n2 = r2 - d1 * d1 - d2 * d2;
    inv = 1.f / fmaxf(sqrtf(fmaxf(n2, 0.f)), 1e-8f);
}

// unpack packed accumulators (t-pairs) to scalar av[4][8]
__device__ __forceinline__ void unpack_av(const ull (&av2)[4][4], float (&av)[4][8]) {
    #pragma unroll
    for (int i = 0; i < 4; i++)
        #pragma unroll
        for (int jp = 0; jp < 4; jp++) {
            float2 f = unpack2(av2[i][jp]);
            av[i][2 * jp] = f.x;
            av[i][2 * jp + 1] = f.y;
        }
}

// ---------------- temporal basis step: all-smem, packed-f32x2 mainloop ----------------
__device__ __forceinline__ void basis_step_t(
    const float4* __restrict__ Tl, const float4* __restrict__ Ts,
    float4* __restrict__ Tn, const float (*Lts)[64],
    float th, float (&accv)[4][8],
    float* red, float* xch, uint32_t xch_addr,
    uint32_t bar0, uint32_t bar1, uint32_t peer, int slot, int parity)
{
    const int tid = threadIdx.x;
    const int n4 = tid >> 3;
    const int t0 = (tid & 7) * 8;
    const bool has_sec = (Ts != nullptr);

    ull av2[4][4];
    #pragma unroll
    for (int i = 0; i < 4; i++)
        #pragma unroll
        for (int j = 0; j < 4; j++) av2[i][j] = 0ull;

    #pragma unroll 8
    for (int k = 0; k < 64; k++) {
        float4 a = Tl[SW(k, n4)];
        ull as[4] = {splat2(a.x), splat2(a.y), splat2(a.z), splat2(a.w)};
        ulonglong2 b01 = *(const ulonglong2*)&Lts[k][t0];      // {b0,b1},{b2,b3}
        ulonglong2 b23 = *(const ulonglong2*)&Lts[k][t0 + 4];  // {b4,b5},{b6,b7}
        ull bp[4] = {b01.x, b01.y, b23.x, b23.y};
        #pragma unroll
        for (int i = 0; i < 4; i++)
            #pragma unroll
            for (int jp = 0; jp < 4; jp++)
                fma2_acc(av2[i][jp], as[i], bp[jp]);
    }
    float av[4][8];
    unpack_av(av2, av);

    float pd1 = 0.f, pd2 = 0.f, pr2 = 0.f;
    #pragma unroll
    for (int j = 0; j < 8; j++) {
        float4 l = Tl[SW(t0 + j, n4)];
        pd1 += av[0][j] * l.x + av[1][j] * l.y + av[2][j] * l.z + av[3][j] * l.w;
    }
    #pragma unroll
    for (int i = 0; i < 4; i++)
        #pragma unroll
        for (int j = 0; j < 8; j++) pr2 = fmaf(av[i][j], av[i][j], pr2);
    if (has_sec) {
        #pragma unroll
        for (int j = 0; j < 8; j++) {
            float4 s = Ts[SW(t0 + j, n4)];
            pd2 += av[0][j] * s.x + av[1][j] * s.y + av[2][j] * s.z + av[3][j] * s.w;
        }
    }
    reduce3(pd1, pd2, pr2, red, slot, tid);
    float d1, d2, inv;
    exchange3(pd1, pd2, pr2, has_sec, xch, xch_addr, bar0, bar1, peer, slot, parity,
              d1, d2, inv, tid);

    #pragma unroll
    for (int j = 0; j < 8; j++) {
        float4 l = Tl[SW(t0 + j, n4)];
        float4 v;
        v.x = av[0][j] - d1 * l.x;
        v.y = av[1][j] - d1 * l.y;
        v.z = av[2][j] - d1 * l.z;
        v.w = av[3][j] - d1 * l.w;
        if (has_sec) {
            float4 s = Ts[SW(t0 + j, n4)];
            v.x -= d2 * s.x; v.y -= d2 * s.y; v.z -= d2 * s.z; v.w -= d2 * s.w;
        }
        v.x *= inv; v.y *= inv; v.z *= inv; v.w *= inv;
        Tn[SW(t0 + j, n4)] = v;
        accv[0][j] = fmaf(th, v.x, accv[0][j]);
        accv[1][j] = fmaf(th, v.y, accv[1][j]);
        accv[2][j] = fmaf(th, v.z, accv[2][j]);
        accv[3][j] = fmaf(th, v.w, accv[3][j]);
    }
    __syncthreads();
}

// ---------------- spatial basis step: global A/B, packed-f32x2 mainloop ----------------
__device__ __forceinline__ void basis_step_s(
    const float* __restrict__ A,
    const float* __restrict__ Bg,
    float* __restrict__ dstg,
    const float* __restrict__ lasth,
    const float* __restrict__ sech,
    float4* __restrict__ Tn,
    float th, float (&accv)[4][8],
    SmemT* sm, float* red, float* xch, uint32_t xch_addr,
    uint32_t bar0, uint32_t bar1, uint32_t peer, int slot, int parity)
{
    // As/Bs staging aliases T[1] (dead during spatial steps)
    float (*As)[16][M_HALF] = (float (*)[16][M_HALF])(&sm->T[1][0]);
    float (*Bs)[16][64]     = (float (*)[16][64])((float*)&sm->T[1][0] + 8192);

    const int tid = threadIdx.x;
    const int rl  = tid >> 1;
    const int kh  = (tid & 1) * 8;
    const int n4  = tid >> 3;
    const int n0  = n4 * 4;
    const int t0  = (tid & 7) * 8;
    const bool has_sec = (sech != nullptr);

    ull av2[4][4];
    #pragma unroll
    for (int i = 0; i < 4; i++)
        #pragma unroll
        for (int j = 0; j < 4; j++) av2[i][j] = 0ull;

    // prologue: stage tile 0
    {
        const float* ar = A + (size_t)rl * 512 + kh;
        float4 a0 = *(const float4*)(ar);
        float4 a1 = *(const float4*)(ar + 4);
        As[0][kh + 0][rl] = a0.x; As[0][kh + 1][rl] = a0.y;
        As[0][kh + 2][rl] = a0.z; As[0][kh + 3][rl] = a0.w;
        As[0][kh + 4][rl] = a1.x; As[0][kh + 5][rl] = a1.y;
        As[0][kh + 6][rl] = a1.z; As[0][kh + 7][rl] = a1.w;
        if (tid < 256)
            ((float4*)&Bs[0][0][0])[tid] = __ldcg((const float4*)Bg + tid);
    }
    __syncthreads();

    int p = 0;
    for (int t = 0; t < 32; t++) {
        float4 na0, na1, nbv;
        const bool more = (t + 1 < 32);
        if (more) {
            const int kt = (t + 1) * 16;
            const float* ar = A + (size_t)rl * 512 + kt + kh;
            na0 = *(const float4*)(ar);
            na1 = *(const float4*)(ar + 4);
            if (tid < 256)
                nbv = __ldcg((const float4*)(Bg + (size_t)kt * 64) + tid);
        }
        #pragma unroll
        for (int k = 0; k < 16; k++) {
            float4 aa = *(const float4*)&As[p][k][n0];
            ull as[4] = {splat2(aa.x), splat2(aa.y), splat2(aa.z), splat2(aa.w)};
            ulonglong2 b01 = *(const ulonglong2*)&Bs[p][k][t0];
            ulonglong2 b23 = *(const ulonglong2*)&Bs[p][k][t0 + 4];
            ull bp[4] = {b01.x, b01.y, b23.x, b23.y};
            #pragma unroll
            for (int i = 0; i < 4; i++)
                #pragma unroll
                for (int jp = 0; jp < 4; jp++)
                    fma2_acc(av2[i][jp], as[i], bp[jp]);
        }
        if (more) {
            const int q = p ^ 1;
            As[q][kh + 0][rl] = na0.x; As[q][kh + 1][rl] = na0.y;
            As[q][kh + 2][rl] = na0.z; As[q][kh + 3][rl] = na0.w;
            As[q][kh + 4][rl] = na1.x; As[q][kh + 5][rl] = na1.y;
            As[q][kh + 6][rl] = na1.z; As[q][kh + 7][rl] = na1.w;
            if (tid < 256) ((float4*)&Bs[q][0][0])[tid] = nbv;
            __syncthreads();
            p = q;
        }
    }
    float av[4][8];
    unpack_av(av2, av);

    // dots + norm
    float pd1 = 0.f, pd2 = 0.f, pr2 = 0.f;
    #pragma unroll
    for (int i = 0; i < 4; i++) {
        int base = (n0 + i) * 64 + t0;
        float4 l0 = *(const float4*)(lasth + base);
        float4 l1 = *(const float4*)(lasth + base + 4);
        float lp[8] = {l0.x, l0.y, l0.z, l0.w, l1.x, l1.y, l1.z, l1.w};
        #pragma unroll
        for (int j = 0; j < 8; j++) {
            pd1 = fmaf(av[i][j], lp[j], pd1);
            pr2 = fmaf(av[i][j], av[i][j], pr2);
        }
        if (has_sec) {
            float4 s0 = *(const float4*)(sech + base);
            float4 s1 = *(const float4*)(sech + base + 4);
            float sp[8] = {s0.x, s0.y, s0.z, s0.w, s1.x, s1.y, s1.z, s1.w};
            #pragma unroll
            for (int j = 0; j < 8; j++) pd2 = fmaf(av[i][j], sp[j], pd2);
        }
    }
    reduce3(pd1, pd2, pr2, red, slot, tid);
    float d1, d2, inv;
    exchange3(pd1, pd2, pr2, has_sec, xch, xch_addr, bar0, bar1, peer, slot, parity,
              d1, d2, inv, tid);

    // write: global rows + transposed T0 + acc regs
    float v[4][8];
    #pragma unroll
    for (int i = 0; i < 4; i++) {
        int base = (n0 + i) * 64 + t0;
        float4 l0 = *(const float4*)(lasth + base);
        float4 l1 = *(const float4*)(lasth + base + 4);
        float lp[8] = {l0.x, l0.y, l0.z, l0.w, l1.x, l1.y, l1.z, l1.w};
        #pragma unroll
        for (int j = 0; j < 8; j++) v[i][j] = av[i][j] - d1 * lp[j];
        if (has_sec) {
            float4 s0 = *(const float4*)(sech + base);
            float4 s1 = *(const float4*)(sech + base + 4);
            float sp[8] = {s0.x, s0.y, s0.z, s0.w, s1.x, s1.y, s1.z, s1.w};
            #pragma unroll
            for (int j = 0; j < 8; j++) v[i][j] -= d2 * sp[j];
        }
        #pragma unroll
        for (int j = 0; j < 8; j++) v[i][j] *= inv;
        *(float4*)(dstg + base)     = make_float4(v[i][0], v[i][1], v[i][2], v[i][3]);
        *(float4*)(dstg + base + 4) = make_float4(v[i][4], v[i][5], v[i][6], v[i][7]);
    }
    #pragma unroll
    for (int j = 0; j < 8; j++)
        Tn[SW(t0 + j, n4)] = make_float4(v[0][j], v[1][j], v[2][j], v[3][j]);
    #pragma unroll
    for (int i = 0; i < 4; i++)
        #pragma unroll
        for (int j = 0; j < 8; j++)
            accv[i][j] = fmaf(th, v[i][j], accv[i][j]);
    __syncthreads();
}

// ---------------- main kernel: 2-CTA cluster per (b,f) slice ----------------
__global__ void __cluster_dims__(2, 1, 1) __launch_bounds__(NTHREADS, 1)
st_main_kernel(const float* __restrict__ x,
               const float* __restrict__ Ls,
               const float* __restrict__ Lt,
               const float* __restrict__ STE,
               const float* __restrict__ w_t1, const float* __restrict__ b_t1,
               const float* __restrict__ w_t2, const float* __restrict__ b_t2)
{
    extern __shared__ __align__(16) char smem_raw[];
    SmemT* sm = reinterpret_cast<SmemT*>(smem_raw);

    __shared__ __align__(16) float red[2 * 64];
    __shared__ float theta_sm[66];
    __shared__ float h1_sm[60];
    __shared__ __align__(16) float xch[8];
    __shared__ __align__(8) unsigned long long mbars[2];

    const int tid = threadIdx.x;
    const int slice = blockIdx.x >> 1;
    const uint32_t rank = blockIdx.x & 1;
    const uint32_t peer = rank ^ 1;
    const int b = slice >> 4;
    const uint32_t xch_addr = smem_u32(xch);
    const uint32_t bar0 = smem_u32(&mbars[0]);
    const uint32_t bar1 = smem_u32(&mbars[1]);
    const size_t hoff = (size_t)rank * HALF;
    const int n4 = tid >> 3;
    const int n0 = n4 * 4;
    const int t0 = (tid & 7) * 8;

    const float* xs = x + (size_t)slice * SLICE;
    float* accg = g_acc + (size_t)slice * SLICE;
    float* bufp[3];
    #pragma unroll
    for (int i = 0; i < 3; i++) bufp[i] = g_bufs + ((size_t)slice * 3 + i) * SLICE;

    if (tid == 0) { mbar_init(bar0, 1); mbar_init(bar1, 1); }
    for (int i = tid; i < 64 * 64 / 4; i += NTHREADS)
        ((float4*)&sm->Lt[0][0])[i] = ((const float4*)Lt)[i];

    if (tid < 60) {
        int o = tid / 10, s = tid % 10;
        float h = b_t1[o];
        #pragma unroll
        for (int t = 0; t < 5; t++) h = fmaf(w_t1[o * 5 + t], STE[b * 50 + t * 10 + s], h);
        h1_sm[o * 10 + s] = h;
    }
    __syncthreads();
    if (tid < 66) {
        int p = tid % 11, o = tid / 11;
        float h = b_t2[p];
        #pragma unroll
        for (int s = 0; s < 10; s++) h = fmaf(w_t2[p * 10 + s], h1_sm[o * 10 + s], h);
        theta_sm[o * 11 + p] = fmaxf(h, 0.f);   // flat r = o*11 + p matches M order
    }
    CLUSTER_SYNC();   // mbarrier init visible cluster-wide before first arrive

    int par01[2] = {0, 0};
    float accv[4][8];

    // ---- step 0: m00 = x / fro(x), into global bufp[0] + T[0] + acc regs ----
    {
        const float* xh = xs + hoff;
        float pnv = 0.f, z1 = 0.f, z2 = 0.f;
        #pragma unroll
        for (int i = 0; i < 4; i++) {
            int base = (n0 + i) * 64 + t0;
            float4 x0 = *(const float4*)(xh + base);
            float4 x1 = *(const float4*)(xh + base + 4);
            pnv += x0.x * x0.x + x0.y * x0.y + x0.z * x0.z + x0.w * x0.w
                 + x1.x * x1.x + x1.y * x1.y + x1.z * x1.z + x1.w * x1.w;
        }
        reduce3(pnv, z1, z2, red, 0, tid);
        float d1, d2, invn;
        exchange3(pnv, 0.f, 0.f, false, xch, xch_addr, bar0, bar1, peer, 0, 0,
                  d1, d2, invn, tid);
        float nv = pnv + xch[0];
        float inv = 1.f / fmaxf(sqrtf(nv), 1e-8f);
        par01[0] ^= 1;
        float th0 = theta_sm[0];
        float* dst0 = bufp[0] + hoff;
        float v[4][8];
        #pragma unroll
        for (int i = 0; i < 4; i++) {
            int base = (n0 + i) * 64 + t0;
            float4 x0 = *(const float4*)(xh + base);
            float4 x1 = *(const float4*)(xh + base + 4);
            v[i][0] = x0.x * inv; v[i][1] = x0.y * inv; v[i][2] = x0.z * inv; v[i][3] = x0.w * inv;
            v[i][4] = x1.x * inv; v[i][5] = x1.y * inv; v[i][6] = x1.z * inv; v[i][7] = x1.w * inv;
            *(float4*)(dst0 + base)     = make_float4(v[i][0], v[i][1], v[i][2], v[i][3]);
            *(float4*)(dst0 + base + 4) = make_float4(v[i][4], v[i][5], v[i][6], v[i][7]);
            #pragma unroll
            for (int j = 0; j < 8; j++) accv[i][j] = th0 * v[i][j];
        }
        #pragma unroll
        for (int j = 0; j < 8; j++)
            sm->T[0][SW(t0 + j, n4)] = make_float4(v[0][j], v[1][j], v[2][j], v[3][j]);
        __syncthreads();
    }

    // ---- recurrence ----
    int last_s = 0, sec_s = -1;   // global spatial chain
    int lastT = 0, secT = -1;     // smem temporal chain
    int r = 1, step = 1;
    for (int i = 0; i <= 10; i++) {
        if (i > 0) {
            int nb = 0;
            while (nb == last_s || nb == sec_s) nb++;
            int slot = step & 1;
            basis_step_s(Ls + (size_t)rank * M_HALF * 512,
                         bufp[last_s],
                         bufp[nb] + hoff,
                         bufp[last_s] + hoff,
                         (sec_s >= 0) ? bufp[sec_s] + hoff : nullptr,
                         sm->T[0], theta_sm[r], accv,
                         sm, red, xch, xch_addr, bar0, bar1, peer, slot, par01[slot]);
            par01[slot] ^= 1;
            sec_s = last_s; last_s = nb;
            lastT = 0; secT = -1;
            r++; step++;
        }
        for (int j = 0; j < 5; j++) {
            int nT = 0;
            while (nT == lastT || nT == secT) nT++;
            int slot = step & 1;
            basis_step_t(sm->T[lastT],
                         (secT >= 0) ? sm->T[secT] : nullptr,
                         sm->T[nT], sm->Lt, theta_sm[r], accv,
                         red, xch, xch_addr, bar0, bar1, peer, slot, par01[slot]);
            par01[slot] ^= 1;
            secT = lastT; lastT = nT;
            r++; step++;
        }
    }

    // ---- write register accumulator to global ----
    float* ah = accg + hoff;
    #pragma unroll
    for (int i = 0; i < 4; i++) {
        int base = (n0 + i) * 64 + t0;
        *(float4*)(ah + base)     = make_float4(accv[i][0], accv[i][1], accv[i][2], accv[i][3]);
        *(float4*)(ah + base + 4) = make_float4(accv[i][4], accv[i][5], accv[i][6], accv[i][7]);
    }
}

// ---------------- output MLP + folded BatchNorm ----------------
__global__ __launch_bounds__(256)
void st_out_kernel(const float* __restrict__ x,
                   const float* __restrict__ w_mlp, const float* __restrict__ b_mlp,
                   const float* __restrict__ gamma, const float* __restrict__ beta,
                   const float* __restrict__ mean, const float* __restrict__ var,
                   float* __restrict__ out)
{
    __shared__ float ws[64][32];
    __shared__ float bs[64];
    const int tid = threadIdx.x;
    for (int i = tid; i < 64 * 32; i += 256) {
        int o = i >> 5;
        float invs = gamma[o] * rsqrtf(var[o] + 1e-5f);
        ws[o][i & 31] = w_mlp[i] * invs;
    }
    if (tid < 64) {
        float invs = gamma[tid] * rsqrtf(var[tid] + 1e-5f);
        bs[tid] = b_mlp[tid] * invs + beta[tid] - mean[tid] * invs;
    }
    __syncthreads();

    const int b = blockIdx.y;
    const int pt = blockIdx.x * 256 + tid;   // 0..32767

    float xv[16], av[16];
    #pragma unroll
    for (int c = 0; c < 16; c++) {
        xv[c] = x[((size_t)(b * 16 + c)) * SLICE + pt];
        av[c] = g_acc[((size_t)(b * 16 + c)) * SLICE + pt];
    }
    #pragma unroll
    for (int o = 0; o < 64; o++) {
        float s = bs[o];
        #pragma unroll
        for (int c = 0; c < 16; c++) {
            s = fmaf(ws[o][c], xv[c], s);
            s = fmaf(ws[o][16 + c], av[c], s);
        }
        out[((size_t)(b * 64 + o)) * SLICE + pt] = s;
    }
}

extern "C" void kernel_launch(void* const* d_in, const int* in_sizes, int n_in,
                              void* d_out, int out_size) {
    const float* x    = (const float*)d_in[0];
    const float* Ls   = (const float*)d_in[1];
    const float* Lt   = (const float*)d_in[2];
    const float* STE  = (const float*)d_in[3];
    const float* w_t1 = (const float*)d_in[4];
    const float* b_t1 = (const float*)d_in[5];
    const float* w_t2 = (const float*)d_in[6];
    const float* b_t2 = (const float*)d_in[7];
    const float* w_mlp = (const float*)d_in[8];
    const float* b_mlp = (const float*)d_in[9];
    const float* gamma = (const float*)d_in[10];
    const float* beta  = (const float*)d_in[11];
    const float* mean  = (const float*)d_in[12];
    const float* var   = (const float*)d_in[13];
    float* out = (float*)d_out;

    cudaFuncSetAttribute(st_main_kernel,
                         cudaFuncAttributeMaxDynamicSharedMemorySize, (int)sizeof(SmemT));
    st_main_kernel<<<NSLICES * 2, NTHREADS, sizeof(SmemT)>>>(
        x, Ls, Lt, STE, w_t1, b_t1, w_t2, b_t2);
    st_out_kernel<<<dim3(128, 4), 256>>>(x, w_mlp, b_mlp, gamma, beta, mean, var, out);
}